// round 9
// baseline (speedup 1.0000x reference)
#include <cuda_runtime.h>
#include <math.h>

#define B_ 16
#define S_ 1024
#define D_ 1024
#define R_ (B_*S_)           // 16384 rows (step-major: r = s*16 + b)
#define CH 16                // steps per chunk
#define NR 256               // rows per chunk
#define NCH 64               // chunks
#define ETA (0.01f * (2.0f/16384.0f))
#define NB 296               // persistent blocks (2 per SM on 148-SM GB300)
#define NT 256               // threads per block
#define BKQ 16               // GEMM K-tile
#define LDS_PAD 8
#define SMW (128 + LDS_PAD)  // 136 floats per smem row
#define SMEMB (4*BKQ*SMW*4)  // As_hi/As_lo/Bs_hi/Bs_lo = 34816 B

// ---------------- scratch (static device globals, ~233 MB) ----------------
static __device__ float g_b0[R_*D_];        // STATE -> TV -> H2
static __device__ float g_b1[R_*D_];        // H -> RD
static __device__ float g_W [D_*D_];
static __device__ float g_Z [NR*D_];
static __device__ float g_E [NR*D_];
static __device__ float g_T [NCH*NR*NR];    // batched per-chunk 256x256 mats
static __device__ float g_T2[NCH*NR*NR];
static __device__ float g_T4[NCH*NR*NR];
static __device__ float g_Sa[NCH*NR*NR];
static __device__ float g_Sb[NCH*NR*NR];    // final Minv
static __device__ float g_Q [NCH*NR*NR];

static __device__ unsigned g_bar_cnt;
static __device__ unsigned g_bar_phase;

__global__ void reset_kernel() {
    if (threadIdx.x == 0) { g_bar_cnt = 0; g_bar_phase = 0; }
}

__device__ __forceinline__ void gsync(unsigned &ph) {
    __syncthreads();
    if (threadIdx.x == 0) {
        ph++;
        __threadfence();
        unsigned a = atomicAdd(&g_bar_cnt, 1);
        if (a == NB - 1) {
            atomicExch(&g_bar_cnt, 0);
            __threadfence();
            atomicExch(&g_bar_phase, ph);
        } else {
            while (atomicAdd(&g_bar_phase, 0) < ph) __nanosleep(100);
        }
        __threadfence();
    }
    __syncthreads();
}

__device__ __forceinline__ float gelu_exact(float v) {
    return 0.5f*v*(1.0f + erff(v*0.70710678118654752440f));
}

// split fp32 into tf32 hi + tf32 lo (3xTF32 trick; ~22-bit effective mantissa)
__device__ __forceinline__ void split_tf32(float v, float &hi, float &lo) {
    unsigned h, l;
    asm("cvt.rna.tf32.f32 %0, %1;" : "=r"(h) : "f"(v));
    float hf = __uint_as_float(h);
    float r  = v - hf;
    asm("cvt.rna.tf32.f32 %0, %1;" : "=r"(l) : "f"(r));
    hi = hf; lo = __uint_as_float(l);
}

__device__ __forceinline__ void mma_tf32(float* c,
    unsigned a0, unsigned a1, unsigned a2, unsigned a3,
    unsigned b0, unsigned b1)
{
    asm volatile(
        "mma.sync.aligned.m16n8k8.row.col.f32.tf32.tf32.f32 "
        "{%0,%1,%2,%3},{%4,%5,%6,%7},{%8,%9},{%0,%1,%2,%3};"
        : "+f"(c[0]), "+f"(c[1]), "+f"(c[2]), "+f"(c[3])
        : "r"(a0), "r"(a1), "r"(a2), "r"(a3), "r"(b0), "r"(b1));
}

// ---------------- TF32 tensor-core GEMM over a grid-strided tile space ------
// C = op(A)@op(B), CTA tile 128x128xBKQ, 8 warps (2x4), warp tile 64x32.
// TA: A stored [K,M]; TB: B stored [N,K]. Row-major everywhere.
// epi: 0: C=alpha*acc   1: C+=alpha*acc
//      2: C=acc - A[r,c] + noise[perm(r0+r),c]        (Z build; nb==1)
//      3: T=-eta*strictBL(acc); Sa(aux)=T+I           (mask A)
//      4: C=-eta*inclBL(acc)                          (mask P -> Q)
//      5: C=acc + aux[idx]                            (S-combine)
//      7: C=gelu(C)*acc + RD[perm] + aux2[idx]        (final gate; nb==1)
template<bool TA, bool TB>
__device__ void dgemm_tc(char* smraw,
                         const float* __restrict__ A0, int sA, int lda,
                         const float* __restrict__ B0, int sB, int ldb,
                         float* C0, int sC, int ldc,
                         int nb, int M, int N, int K,
                         float alpha, int epi,
                         float* aux, int sAux, const float* __restrict__ aux2, int r0)
{
    float* AsH = (float*)smraw;
    float* AsL = AsH + BKQ*SMW;
    float* BsH = AsL + BKQ*SMW;
    float* BsL = BsH + BKQ*SMW;

    const int tid  = threadIdx.x;
    const int lane = tid & 31;
    const int wid  = tid >> 5;
    const int wm   = wid >> 2;      // 0..1
    const int wn   = wid & 3;       // 0..3
    const int gq   = lane >> 2;     // groupID 0..7
    const int tg   = lane & 3;      // threadID_in_group 0..3

    const int tpmN = N >> 7;
    const int tpm  = (M >> 7) * tpmN;
    const int ntiles = nb * tpm;

    for (int t = blockIdx.x; t < ntiles; t += NB) {
        const int cb = t / tpm;
        const int tt = t - cb*tpm;
        const int bm = tt / tpmN;
        const int bn = tt - bm*tpmN;
        const int m0 = bm << 7, n0 = bn << 7;
        const float* A = A0 + (long)cb*sA;
        const float* B = B0 + (long)cb*sB;
        float*       C = C0 + (long)cb*sC;
        float*    auxc = aux ? (aux + (long)cb*sAux) : (float*)0;

        float acc[4][4][4];
        #pragma unroll
        for (int i=0;i<4;i++)
            #pragma unroll
            for (int j=0;j<4;j++)
                #pragma unroll
                for (int q=0;q<4;q++) acc[i][j][q]=0.f;

        for (int k0 = 0; k0 < K; k0 += BKQ) {
            // ---- stage + split A, B tiles ----
            #pragma unroll
            for (int it = 0; it < (128*BKQ)/NT; it++) {
                int i = tid + it*NT;
                float v; int kk, mm;
                if (!TA) { mm = i >> 4; kk = i & 15; v = A[(long)(m0+mm)*lda + (k0+kk)]; }
                else     { kk = i >> 7; mm = i & 127; v = A[(long)(k0+kk)*lda + (m0+mm)]; }
                float h,l; split_tf32(v,h,l);
                AsH[kk*SMW+mm] = h; AsL[kk*SMW+mm] = l;
            }
            #pragma unroll
            for (int it = 0; it < (128*BKQ)/NT; it++) {
                int i = tid + it*NT;
                float v; int kk, nn;
                if (!TB) { kk = i >> 7; nn = i & 127; v = B[(long)(k0+kk)*ldb + (n0+nn)]; }
                else     { nn = i >> 4; kk = i & 15; v = B[(long)(n0+nn)*ldb + (k0+kk)]; }
                float h,l; split_tf32(v,h,l);
                BsH[kk*SMW+nn] = h; BsL[kk*SMW+nn] = l;
            }
            __syncthreads();

            // ---- tensor-core mainloop: 2 k8 steps ----
            #pragma unroll
            for (int k8 = 0; k8 < BKQ; k8 += 8) {
                unsigned bh0[4], bh1[4], bl0[4], bl1[4];
                #pragma unroll
                for (int nt=0; nt<4; nt++) {
                    int bnc = wn*32 + nt*8 + gq;
                    bh0[nt] = __float_as_uint(BsH[(k8+tg  )*SMW + bnc]);
                    bh1[nt] = __float_as_uint(BsH[(k8+tg+4)*SMW + bnc]);
                    bl0[nt] = __float_as_uint(BsL[(k8+tg  )*SMW + bnc]);
                    bl1[nt] = __float_as_uint(BsL[(k8+tg+4)*SMW + bnc]);
                }
                #pragma unroll
                for (int mt=0; mt<4; mt++) {
                    int am = wm*64 + mt*16 + gq;
                    unsigned ah0 = __float_as_uint(AsH[(k8+tg  )*SMW + am]);
                    unsigned ah1 = __float_as_uint(AsH[(k8+tg  )*SMW + am+8]);
                    unsigned ah2 = __float_as_uint(AsH[(k8+tg+4)*SMW + am]);
                    unsigned ah3 = __float_as_uint(AsH[(k8+tg+4)*SMW + am+8]);
                    unsigned al0 = __float_as_uint(AsL[(k8+tg  )*SMW + am]);
                    unsigned al1 = __float_as_uint(AsL[(k8+tg  )*SMW + am+8]);
                    unsigned al2 = __float_as_uint(AsL[(k8+tg+4)*SMW + am]);
                    unsigned al3 = __float_as_uint(AsL[(k8+tg+4)*SMW + am+8]);
                    #pragma unroll
                    for (int nt=0; nt<4; nt++) {
                        mma_tf32(acc[mt][nt], ah0,ah1,ah2,ah3, bh0[nt],bh1[nt]);
                        mma_tf32(acc[mt][nt], ah0,ah1,ah2,ah3, bl0[nt],bl1[nt]);
                        mma_tf32(acc[mt][nt], al0,al1,al2,al3, bh0[nt],bh1[nt]);
                    }
                }
            }
            __syncthreads();
        }

        // ---- elementwise epilogue over fragment (r,c) mapping ----
        #pragma unroll
        for (int mt=0; mt<4; mt++) {
            #pragma unroll
            for (int nt=0; nt<4; nt++) {
                #pragma unroll
                for (int rg=0; rg<4; rg++) {
                    int r = m0 + wm*64 + mt*16 + gq + ((rg>>1)?8:0);
                    int c = n0 + wn*32 + nt*8  + 2*tg + (rg&1);
                    float v = acc[mt][nt][rg];
                    long idx = (long)r*ldc + c;
                    if (epi == 0) {
                        C[idx] = alpha*v;
                    } else if (epi == 1) {
                        C[idx] += alpha*v;
                    } else if (epi == 2) {
                        int gr = r0 + r; int s = gr>>4, b = gr&15;
                        C[idx] = v - A[(long)r*lda + c] + aux2[((long)b*S_+s)*D_ + c];
                    } else if (epi == 3) {
                        float tv = ((r>>4)>(c>>4)) ? (-ETA)*v : 0.f;
                        C[idx] = tv; auxc[idx] = tv + ((r==c)?1.f:0.f);
                    } else if (epi == 4) {
                        C[idx] = ((r>>4)>=(c>>4)) ? (-ETA)*v : 0.f;
                    } else if (epi == 5) {
                        C[idx] = v + auxc[idx];
                    } else { // epi == 7
                        int b = r/S_, s = r - b*S_;
                        float u = C[idx];
                        C[idx] = gelu_exact(u)*v + g_b1[((long)(s*16+b))*D_ + c] + aux2[idx];
                    }
                }
            }
        }
    }
}

#define DG_NT dgemm_tc<false,true>
#define DG_NN dgemm_tc<false,false>
#define DG_TN dgemm_tc<true,false>

// ---------------- the mega-kernel ----------------
__global__ void __launch_bounds__(NT, 2)
mega(const float* __restrict__ x, const float* __restrict__ noise,
     const float* __restrict__ alpha1, const float* __restrict__ alpha2,
     const float* __restrict__ Wmap, const float* __restrict__ Wstate,
     const float* __restrict__ Wprobe, const float* __restrict__ Wp1,
     const float* __restrict__ Wp2, float* __restrict__ out)
{
    __shared__ __align__(16) char sm[SMEMB];
    unsigned ph = 0;
    const long tstep = (long)NB*NT;
    const long gt0 = (long)blockIdx.x*NT + threadIdx.x;

    // ph0: W copy + H = tanh(alpha1*x) (step-major permuted)
    for (long g = gt0; g < (long)D_*D_/4; g += tstep)
        *(float4*)(g_W + g*4) = *(const float4*)(Wmap + g*4);
    for (long g = gt0; g < (long)R_*D_/4; g += tstep) {
        int d4 = (int)(g % (D_/4)); int r = (int)(g / (D_/4));
        int s = r >> 4, b = r & 15;
        float4 xv = *(const float4*)(x + ((long)b*S_ + s)*D_ + (long)d4*4);
        float4 a  = *(const float4*)(alpha1 + (long)d4*4);
        float4 h;
        h.x = tanhf(a.x*xv.x); h.y = tanhf(a.y*xv.y);
        h.z = tanhf(a.z*xv.z); h.w = tanhf(a.w*xv.w);
        *(float4*)(g_b1 + (long)r*D_ + (long)d4*4) = h;
    }
    gsync(ph);

    // ph1: STATE = H@Ws^T -> b0 ; PROBE = H@Wp^T -> out
    DG_NT(sm, g_b1,0,D_, Wstate,0,D_, g_b0,0,D_, 1, R_,D_,D_, 1.f, 0, nullptr,0,nullptr,0);
    DG_NT(sm, g_b1,0,D_, Wprobe,0,D_, out, 0,D_, 1, R_,D_,D_, 1.f, 0, nullptr,0,nullptr,0);
    gsync(ph);

    // ph2: TV = STATE + noise (permuted), in place
    for (long g = gt0; g < (long)R_*D_/4; g += tstep) {
        int d4 = (int)(g % (D_/4)); int r = (int)(g / (D_/4));
        int s = r >> 4, b = r & 15;
        float4 st = *(const float4*)(g_b0 + (long)r*D_ + (long)d4*4);
        float4 nz = *(const float4*)(noise + ((long)b*S_ + s)*D_ + (long)d4*4);
        st.x += nz.x; st.y += nz.y; st.z += nz.z; st.w += nz.w;
        *(float4*)(g_b0 + (long)r*D_ + (long)d4*4) = st;
    }
    gsync(ph);

    // ph3 (batched over 64 chunks): A=TV@TV^T -> T,Sa(masked);  P=PROBE@TV^T -> Q(masked)
    DG_NT(sm, g_b0,NR*D_,D_, g_b0,NR*D_,D_, g_T,NR*NR,NR, NCH, NR,NR,D_, 1.f, 3, g_Sa,NR*NR, nullptr,0);
    DG_NT(sm, out, NR*D_,D_, g_b0,NR*D_,D_, g_Q,NR*NR,NR, NCH, NR,NR,D_, 1.f, 4, nullptr,0, nullptr,0);
    gsync(ph);

    // Minv = (I+T)(I+T^2)(I+T^4)(I+T^8), batched (exact: T^16 = 0)
    DG_NN(sm, g_T,NR*NR,NR, g_T,NR*NR,NR, g_T2,NR*NR,NR, NCH, NR,NR,NR, 1.f, 0, nullptr,0,nullptr,0);   // T2
    gsync(ph);
    DG_NN(sm, g_Sa,NR*NR,NR, g_T2,NR*NR,NR, g_Sb,NR*NR,NR, NCH, NR,NR,NR, 1.f, 5, g_Sa,NR*NR, nullptr,0); // Sb=Sa(I+T2)
    DG_NN(sm, g_T2,NR*NR,NR, g_T2,NR*NR,NR, g_T4,NR*NR,NR, NCH, NR,NR,NR, 1.f, 0, nullptr,0,nullptr,0);   // T4
    gsync(ph);
    DG_NN(sm, g_Sb,NR*NR,NR, g_T4,NR*NR,NR, g_Sa,NR*NR,NR, NCH, NR,NR,NR, 1.f, 5, g_Sb,NR*NR, nullptr,0); // Sa=Sb(I+T4)
    DG_NN(sm, g_T4,NR*NR,NR, g_T4,NR*NR,NR, g_T2,NR*NR,NR, NCH, NR,NR,NR, 1.f, 0, nullptr,0,nullptr,0);   // T8 (in T2)
    gsync(ph);
    DG_NN(sm, g_Sa,NR*NR,NR, g_T2,NR*NR,NR, g_Sb,NR*NR,NR, NCH, NR,NR,NR, 1.f, 5, g_Sa,NR*NR, nullptr,0); // Minv in Sb
    gsync(ph);

    // Sequential W-dependent loop: 3 phases per chunk
    for (int c = 0; c < NCH; c++) {
        const int off = c*NR*D_, bo = c*NR*NR;
        // ph_a: Z = TVc@W^T - TVc + noise_c ; RDbase = PROBEc@W^T
        DG_NT(sm, g_b0+off,0,D_, g_W,0,D_, g_Z,0,D_, 1, NR,D_,D_, 1.f, 2, nullptr,0, noise, c*NR);
        DG_NT(sm, out+off, 0,D_, g_W,0,D_, g_b1+off,0,D_, 1, NR,D_,D_, 1.f, 0, nullptr,0,nullptr,0);
        gsync(ph);
        // ph_b: E = Minv_c @ Z
        DG_NN(sm, g_Sb+bo,0,NR, g_Z,0,D_, g_E,0,D_, 1, NR,D_,NR, 1.f, 0, nullptr,0,nullptr,0);
        gsync(ph);
        // ph_c: RD += Q_c @ E ; W += -eta * E^T @ TVc
        DG_NN(sm, g_Q+bo,0,NR, g_E,0,D_, g_b1+off,0,D_, 1, NR,D_,NR, 1.f, 1, nullptr,0,nullptr,0);
        DG_TN(sm, g_E,0,D_, g_b0+off,0,D_, g_W,0,D_, 1, D_,D_,NR, -ETA, 1, nullptr,0,nullptr,0);
        gsync(ph);
    }

    // ph8: H2 = tanh(alpha2*(RD[perm] + x)) -> b0 (row-major r = b*S+s)
    for (long g = gt0; g < (long)R_*D_/4; g += tstep) {
        int d4 = (int)(g % (D_/4)); int r = (int)(g / (D_/4));
        int b = r / S_, s = r - b*S_;
        float4 rd = *(const float4*)(g_b1 + ((long)(s*16+b))*D_ + (long)d4*4);
        float4 xv = *(const float4*)(x + (long)r*D_ + (long)d4*4);
        float4 a2 = *(const float4*)(alpha2 + (long)d4*4);
        float4 h2;
        h2.x = tanhf(a2.x*(rd.x+xv.x)); h2.y = tanhf(a2.y*(rd.y+xv.y));
        h2.z = tanhf(a2.z*(rd.z+xv.z)); h2.w = tanhf(a2.w*(rd.w+xv.w));
        *(float4*)(g_b0 + (long)r*D_ + (long)d4*4) = h2;
    }
    gsync(ph);

    // ph9: U = H2@Wp1^T -> out
    DG_NT(sm, g_b0,0,D_, Wp1,0,D_, out,0,D_, 1, R_,D_,D_, 1.f, 0, nullptr,0,nullptr,0);
    gsync(ph);

    // ph10: out = gelu(U) * (H2@Wp2^T) + RD[perm] + x
    DG_NT(sm, g_b0,0,D_, Wp2,0,D_, out,0,D_, 1, R_,D_,D_, 1.f, 7, nullptr,0, x, 0);
}

extern "C" void kernel_launch(void* const* d_in, const int* in_sizes, int n_in,
                              void* d_out, int out_size) {
    const float* x       = (const float*)d_in[0];
    const float* noise   = (const float*)d_in[1];
    const float* alpha1  = (const float*)d_in[2];
    const float* alpha2  = (const float*)d_in[3];
    const float* W_map   = (const float*)d_in[4];
    const float* W_state = (const float*)d_in[5];
    const float* W_probe = (const float*)d_in[6];
    const float* W_p1    = (const float*)d_in[7];
    const float* W_p2    = (const float*)d_in[8];
    float* out = (float*)d_out;

    reset_kernel<<<1, 32>>>();
    mega<<<NB, NT>>>(x, noise, alpha1, alpha2, W_map, W_state, W_probe, W_p1, W_p2, out);
}

// round 10
// speedup vs baseline: 1.7179x; 1.7179x over previous
#include <cuda_runtime.h>
#include <cuda_bf16.h>
#include <math.h>

#define B_ 16
#define S_ 1024
#define D_ 1024
#define R_ (B_*S_)           // 16384 rows (step-major: r = s*16 + b)
#define NR 256               // rows per chunk (16 steps x 16 batch)
#define NCH 64               // chunks
#define ETA (0.01f * (2.0f/16384.0f))
#define NB 296               // persistent blocks (2/SM on 148-SM GB300)
#define NT 256
#define SMS 12               // smem row stride in 32-bit words (conflict-free)
#define SMEMB (4*128*SMS*4)  // AsH/AsL/BsH/BsL = 24576 B

// ---------------- scratch (static device globals, ~310 MB) ----------------
static __device__ float g_b0 [R_*D_];       // STATE -> TV -> H2
static __device__ float g_b1 [R_*D_];       // H -> RD
static __device__ float g_TVT[D_*R_];       // TV transposed [D][R]
static __device__ float g_W  [D_*D_];
static __device__ float g_ZT [D_*NR];       // Z^T per chunk
static __device__ float g_ET [D_*NR];       // E^T per chunk
static __device__ float g_T  [NCH*NR*NR];
static __device__ float g_TT [NCH*NR*NR];
static __device__ float g_T2 [NCH*NR*NR];
static __device__ float g_CT2[NCH*NR*NR];
static __device__ float g_Sa [NCH*NR*NR];
static __device__ float g_Sb [NCH*NR*NR];   // final Minv
static __device__ float g_Q  [NCH*NR*NR];

static __device__ unsigned g_bar_cnt;
static __device__ unsigned g_bar_phase;

__global__ void reset_kernel() {
    if (threadIdx.x == 0) { g_bar_cnt = 0; g_bar_phase = 0; }
}

__device__ __forceinline__ void gsync(unsigned &ph) {
    __syncthreads();
    if (threadIdx.x == 0) {
        ph++;
        __threadfence();
        unsigned a = atomicAdd(&g_bar_cnt, 1);
        if (a == NB - 1) {
            atomicExch(&g_bar_cnt, 0);
            __threadfence();
            atomicExch(&g_bar_phase, ph);
        } else {
            while (atomicAdd(&g_bar_phase, 0) < ph) __nanosleep(100);
        }
        __threadfence();
    }
    __syncthreads();
}

__device__ __forceinline__ float gelu_exact(float v) {
    return 0.5f*v*(1.0f + erff(v*0.70710678118654752440f));
}

// pack two floats to bf16x2 (hi) and return residuals for the lo plane
__device__ __forceinline__ unsigned pack_hi(float a, float b, float &ra, float &rb) {
    __nv_bfloat16 ha = __float2bfloat16_rn(a);
    __nv_bfloat16 hb = __float2bfloat16_rn(b);
    ra = a - __bfloat162float(ha);
    rb = b - __bfloat162float(hb);
    return ((unsigned)__bfloat16_as_ushort(hb) << 16) | (unsigned)__bfloat16_as_ushort(ha);
}
__device__ __forceinline__ unsigned pack_lo(float a, float b) {
    return ((unsigned)__bfloat16_as_ushort(__float2bfloat16_rn(b)) << 16)
         |  (unsigned)__bfloat16_as_ushort(__float2bfloat16_rn(a));
}

__device__ __forceinline__ void mma_bf16(float* c,
    unsigned a0, unsigned a1, unsigned a2, unsigned a3, unsigned b0, unsigned b1)
{
    asm volatile(
        "mma.sync.aligned.m16n8k16.row.col.f32.bf16.bf16.f32 "
        "{%0,%1,%2,%3},{%4,%5,%6,%7},{%8,%9},{%0,%1,%2,%3};"
        : "+f"(c[0]), "+f"(c[1]), "+f"(c[2]), "+f"(c[3])
        : "r"(a0), "r"(a1), "r"(a2), "r"(a3), "r"(b0), "r"(b1));
}

// ---------------- bf16-split NT GEMM, grid-strided tile space ----------------
// C = op: A[M][K] @ B[N][K]^T. CTA tile 128x128x16, 8 warps (2x4), warp 64x32.
// Writes: C (normal, ldc) if C0 != null; CT (transposed, ldct) if CT0 != null.
// epi: 0: C=alpha*acc (and/or CT)      1: C += alpha*acc
//      2: val=acc - A[r,c] + noise[perm(r0+r),c]; write CT only   (Z build)
//      3: T=-eta*strictBL(acc) -> C and CT; aux=T+I               (mask A)
//      4: C=-eta*inclBL(acc)                                      (mask P->Q)
//      5: C=acc + aux[idx]                                        (S-combine)
//      7: C=gelu(C)*acc + RD[perm] + aux2[idx]                    (final gate)
__device__ void dgemm_nt(char* smraw,
    const float* __restrict__ A0, long sA, int lda,
    const float* __restrict__ B0, long sB, int ldb,
    float* C0, long sC, int ldc,
    float* CT0, long sCT, int ldct,
    int nb, int M, int N, int K,
    float alpha, int epi,
    float* aux, long sAux, const float* __restrict__ aux2, int r0)
{
    float* AsH = (float*)smraw;
    float* AsL = AsH + 128*SMS;
    float* BsH = AsL + 128*SMS;
    float* BsL = BsH + 128*SMS;

    const int tid  = threadIdx.x;
    const int lane = tid & 31;
    const int wid  = tid >> 5;
    const int wm   = wid >> 2;     // 0..1
    const int wn   = wid & 3;      // 0..3
    const int gq   = lane >> 2;    // 0..7
    const int tg   = lane & 3;     // 0..3

    const int srow = tid >> 1;            // staging row 0..127
    const int sk8  = (tid & 1) << 3;      // staging k offset 0/8
    const int sk2  = sk8 >> 1;            // word offset 0/4

    const int tpmN = N >> 7;
    const int tpm  = (M >> 7) * tpmN;
    const int ntiles = nb * tpm;

    for (int t = blockIdx.x; t < ntiles; t += NB) {
        const int cb = t / tpm;
        const int tt = t - cb*tpm;
        const int bm = tt / tpmN;
        const int bn = tt - bm*tpmN;
        const int m0 = bm << 7, n0 = bn << 7;
        const float* A = A0 + (long)cb*sA;
        const float* B = B0 + (long)cb*sB;

        const float* Arow = A + (long)(m0 + srow)*lda + sk8;
        const float* Brow = B + (long)(n0 + srow)*ldb + sk8;

        float acc[4][4][4];
        #pragma unroll
        for (int i=0;i<4;i++)
            #pragma unroll
            for (int j=0;j<4;j++)
                #pragma unroll
                for (int q=0;q<4;q++) acc[i][j][q]=0.f;

        float4 pa0 = *(const float4*)(Arow);
        float4 pa1 = *(const float4*)(Arow + 4);
        float4 pb0 = *(const float4*)(Brow);
        float4 pb1 = *(const float4*)(Brow + 4);

        for (int k0 = 0; k0 < K; k0 += 16) {
            // ---- convert prefetched regs -> smem (hi/lo planes) ----
            {
                float r0_,r1_,r2_,r3_,r4_,r5_,r6_,r7_;
                uint4 hv, lv;
                hv.x = pack_hi(pa0.x, pa0.y, r0_, r1_);
                hv.y = pack_hi(pa0.z, pa0.w, r2_, r3_);
                hv.z = pack_hi(pa1.x, pa1.y, r4_, r5_);
                hv.w = pack_hi(pa1.z, pa1.w, r6_, r7_);
                lv.x = pack_lo(r0_, r1_); lv.y = pack_lo(r2_, r3_);
                lv.z = pack_lo(r4_, r5_); lv.w = pack_lo(r6_, r7_);
                *(uint4*)(AsH + srow*SMS + sk2) = hv;
                *(uint4*)(AsL + srow*SMS + sk2) = lv;
                hv.x = pack_hi(pb0.x, pb0.y, r0_, r1_);
                hv.y = pack_hi(pb0.z, pb0.w, r2_, r3_);
                hv.z = pack_hi(pb1.x, pb1.y, r4_, r5_);
                hv.w = pack_hi(pb1.z, pb1.w, r6_, r7_);
                lv.x = pack_lo(r0_, r1_); lv.y = pack_lo(r2_, r3_);
                lv.z = pack_lo(r4_, r5_); lv.w = pack_lo(r6_, r7_);
                *(uint4*)(BsH + srow*SMS + sk2) = hv;
                *(uint4*)(BsL + srow*SMS + sk2) = lv;
            }
            __syncthreads();
            // ---- prefetch next k-slab (overlaps compute below) ----
            if (k0 + 16 < K) {
                pa0 = *(const float4*)(Arow + k0 + 16);
                pa1 = *(const float4*)(Arow + k0 + 20);
                pb0 = *(const float4*)(Brow + k0 + 16);
                pb1 = *(const float4*)(Brow + k0 + 20);
            }
            // ---- one k16 step: 48 MMAs ----
            unsigned bh[4][2], bl[4][2];
            #pragma unroll
            for (int nt=0; nt<4; nt++) {
                int bnr = (wn*32 + nt*8 + gq)*SMS;
                bh[nt][0] = __float_as_uint(BsH[bnr + tg]);
                bh[nt][1] = __float_as_uint(BsH[bnr + tg + 4]);
                bl[nt][0] = __float_as_uint(BsL[bnr + tg]);
                bl[nt][1] = __float_as_uint(BsL[bnr + tg + 4]);
            }
            #pragma unroll
            for (int mt=0; mt<4; mt++) {
                int am = (wm*64 + mt*16 + gq)*SMS;
                unsigned ah0 = __float_as_uint(AsH[am + tg]);
                unsigned ah1 = __float_as_uint(AsH[am + 8*SMS + tg]);
                unsigned ah2 = __float_as_uint(AsH[am + tg + 4]);
                unsigned ah3 = __float_as_uint(AsH[am + 8*SMS + tg + 4]);
                unsigned al0 = __float_as_uint(AsL[am + tg]);
                unsigned al1 = __float_as_uint(AsL[am + 8*SMS + tg]);
                unsigned al2 = __float_as_uint(AsL[am + tg + 4]);
                unsigned al3 = __float_as_uint(AsL[am + 8*SMS + tg + 4]);
                #pragma unroll
                for (int nt=0; nt<4; nt++) {
                    mma_bf16(acc[mt][nt], ah0,ah1,ah2,ah3, bh[nt][0],bh[nt][1]);
                    mma_bf16(acc[mt][nt], ah0,ah1,ah2,ah3, bl[nt][0],bl[nt][1]);
                    mma_bf16(acc[mt][nt], al0,al1,al2,al3, bh[nt][0],bh[nt][1]);
                }
            }
            __syncthreads();
        }

        // ---- epilogue over fragment (r,c) mapping ----
        float* C   = C0  ? (C0  + (long)cb*sC)   : (float*)0;
        float* CT  = CT0 ? (CT0 + (long)cb*sCT)  : (float*)0;
        float* auxc = aux ? (aux + (long)cb*sAux) : (float*)0;
        #pragma unroll
        for (int mt=0; mt<4; mt++) {
            #pragma unroll
            for (int nt=0; nt<4; nt++) {
                #pragma unroll
                for (int rg=0; rg<4; rg++) {
                    int r = m0 + wm*64 + mt*16 + gq + ((rg>>1)?8:0);
                    int c = n0 + wn*32 + nt*8  + 2*tg + (rg&1);
                    float v = acc[mt][nt][rg];
                    long idx = (long)r*ldc + c;
                    if (epi == 2) {
                        int gr = r0 + r; int s = gr>>4, b = gr&15;
                        CT[(long)c*ldct + r] =
                            v - A[(long)r*lda + c] + aux2[((long)b*S_+s)*D_ + c];
                    } else if (epi == 3) {
                        float tv = ((r>>4)>(c>>4)) ? (-ETA)*v : 0.f;
                        C[idx] = tv;
                        CT[(long)c*ldct + r] = tv;
                        auxc[idx] = tv + ((r==c)?1.f:0.f);
                    } else if (epi == 4) {
                        C[idx] = ((r>>4)>=(c>>4)) ? (-ETA)*v : 0.f;
                    } else if (epi == 5) {
                        C[idx] = v + auxc[idx];
                    } else if (epi == 7) {
                        int b = r/S_, s = r - b*S_;
                        float u = C[idx];
                        C[idx] = gelu_exact(u)*v + g_b1[((long)(s*16+b))*D_ + c] + aux2[idx];
                    } else if (epi == 1) {
                        C[idx] += alpha*v;
                    } else { // epi == 0
                        float val = alpha*v;
                        if (C)  C[idx] = val;
                        if (CT) CT[(long)c*ldct + r] = val;
                    }
                }
            }
        }
    }
}

#define NOC (float*)0, 0L, 0
#define NOAUX (float*)0, 0L, (const float*)0, 0

// ---------------- the mega-kernel ----------------
__global__ void __launch_bounds__(NT, 2)
mega(const float* __restrict__ x, const float* __restrict__ noise,
     const float* __restrict__ alpha1, const float* __restrict__ alpha2,
     const float* __restrict__ Wmap, const float* __restrict__ Wstate,
     const float* __restrict__ Wprobe, const float* __restrict__ Wp1,
     const float* __restrict__ Wp2, float* __restrict__ out)
{
    __shared__ __align__(16) char sm[SMEMB];
    unsigned ph = 0;
    const long tstep = (long)NB*NT;
    const long gt0 = (long)blockIdx.x*NT + threadIdx.x;

    // ph0: W copy + H = tanh(alpha1*x) (step-major permuted) -> b1
    for (long g = gt0; g < (long)D_*D_/4; g += tstep)
        *(float4*)(g_W + g*4) = *(const float4*)(Wmap + g*4);
    for (long g = gt0; g < (long)R_*D_/4; g += tstep) {
        int d4 = (int)(g % (D_/4)); int r = (int)(g / (D_/4));
        int s = r >> 4, b = r & 15;
        float4 xv = *(const float4*)(x + ((long)b*S_ + s)*D_ + (long)d4*4);
        float4 a  = *(const float4*)(alpha1 + (long)d4*4);
        float4 h;
        h.x = tanhf(a.x*xv.x); h.y = tanhf(a.y*xv.y);
        h.z = tanhf(a.z*xv.z); h.w = tanhf(a.w*xv.w);
        *(float4*)(g_b1 + (long)r*D_ + (long)d4*4) = h;
    }
    gsync(ph);

    // ph1: STATE = H@Ws^T -> b0 ; PROBE = H@Wp^T -> out
    dgemm_nt(sm, g_b1,0,D_, Wstate,0,D_, g_b0,0,D_, NOC, 1, R_,D_,D_, 1.f, 0, NOAUX);
    dgemm_nt(sm, g_b1,0,D_, Wprobe,0,D_, out, 0,D_, NOC, 1, R_,D_,D_, 1.f, 0, NOAUX);
    gsync(ph);

    // ph2: TV = STATE + noise (in place) AND TVT transpose (tiled 32x32)
    {
        float (*ts)[33] = (float (*)[33])sm;
        const int rl = threadIdx.x >> 3;
        const int c4 = (threadIdx.x & 7) << 2;
        for (int t = blockIdx.x; t < (R_/32)*(D_/32); t += NB) {
            int rt = t >> 5;         // D_/32 = 32 tiles along d
            int ct = t & 31;
            long gr = (long)rt*32 + rl;
            int s = (int)(gr>>4), b = (int)(gr&15);
            float4 st = *(const float4*)(g_b0 + gr*D_ + ct*32 + c4);
            float4 nz = *(const float4*)(noise + ((long)b*S_+s)*D_ + ct*32 + c4);
            st.x+=nz.x; st.y+=nz.y; st.z+=nz.z; st.w+=nz.w;
            *(float4*)(g_b0 + gr*D_ + ct*32 + c4) = st;
            ts[rl][c4+0]=st.x; ts[rl][c4+1]=st.y; ts[rl][c4+2]=st.z; ts[rl][c4+3]=st.w;
            __syncthreads();
            float4 o;
            o.x = ts[c4+0][rl]; o.y = ts[c4+1][rl];
            o.z = ts[c4+2][rl]; o.w = ts[c4+3][rl];
            *(float4*)(g_TVT + ((long)ct*32 + rl)*R_ + (long)rt*32 + c4) = o;
            __syncthreads();
        }
    }
    gsync(ph);

    // ph3 (batched): A=TV@TV^T -> T,TT,Sa (epi3);  P=PROBE@TV^T -> Q (epi4)
    dgemm_nt(sm, g_b0,NR*D_,D_, g_b0,NR*D_,D_, g_T,NR*NR,NR, g_TT,NR*NR,NR,
             NCH, NR,NR,D_, 1.f, 3, g_Sa,NR*NR, (const float*)0,0);
    dgemm_nt(sm, out, NR*D_,D_, g_b0,NR*D_,D_, g_Q,NR*NR,NR, NOC,
             NCH, NR,NR,D_, 1.f, 4, NOAUX);
    gsync(ph);

    // Minv = (I+T)(I+T^2)(I+T^4)(I+T^8), batched (exact: T^16 = 0)
    dgemm_nt(sm, g_T,NR*NR,NR, g_TT,NR*NR,NR, g_T2,NR*NR,NR, g_CT2,NR*NR,NR,
             NCH, NR,NR,NR, 1.f, 0, NOAUX);                                   // T2, T2T
    gsync(ph);
    dgemm_nt(sm, g_Sa,NR*NR,NR, g_CT2,NR*NR,NR, g_Sb,NR*NR,NR, NOC,
             NCH, NR,NR,NR, 1.f, 5, g_Sa,NR*NR, (const float*)0,0);           // Sb=Sa(I+T2)
    dgemm_nt(sm, g_T2,NR*NR,NR, g_CT2,NR*NR,NR, g_T,NR*NR,NR, g_TT,NR*NR,NR,
             NCH, NR,NR,NR, 1.f, 0, NOAUX);                                   // T4, T4T
    gsync(ph);
    dgemm_nt(sm, g_Sb,NR*NR,NR, g_TT,NR*NR,NR, g_Sa,NR*NR,NR, NOC,
             NCH, NR,NR,NR, 1.f, 5, g_Sb,NR*NR, (const float*)0,0);           // Sa=Sb(I+T4)
    dgemm_nt(sm, g_T,NR*NR,NR, g_TT,NR*NR,NR, (float*)0,0,0, g_T2,NR*NR,NR,
             NCH, NR,NR,NR, 1.f, 0, NOAUX);                                   // T8T only
    gsync(ph);
    dgemm_nt(sm, g_Sa,NR*NR,NR, g_T2,NR*NR,NR, g_Sb,NR*NR,NR, NOC,
             NCH, NR,NR,NR, 1.f, 5, g_Sa,NR*NR, (const float*)0,0);           // Minv in Sb
    gsync(ph);

    // Sequential W-dependent loop: 3 phases per chunk
    for (int c = 0; c < NCH; c++) {
        const long off = (long)c*NR*D_;
        const long bo  = (long)c*NR*NR;
        // ph_a: ZT = (TVc@W^T - TVc + noise_c)^T ; RDbase = PROBEc@W^T
        dgemm_nt(sm, g_b0+off,0,D_, g_W,0,D_, (float*)0,0,0, g_ZT,0,NR,
                 1, NR,D_,D_, 1.f, 2, (float*)0,0, noise, c*NR);
        dgemm_nt(sm, out+off,0,D_, g_W,0,D_, g_b1+off,0,D_, NOC,
                 1, NR,D_,D_, 1.f, 0, NOAUX);
        gsync(ph);
        // ph_b: ET = (Minv_c @ Z)^T
        dgemm_nt(sm, g_Sb+bo,0,NR, g_ZT,0,NR, (float*)0,0,0, g_ET,0,NR,
                 1, NR,D_,NR, 1.f, 0, NOAUX);
        gsync(ph);
        // ph_c: RD += Q_c @ E ; W += -eta * E^T @ TVc
        dgemm_nt(sm, g_Q+bo,0,NR, g_ET,0,NR, g_b1+off,0,D_, NOC,
                 1, NR,D_,NR, 1.f, 1, NOAUX);
        dgemm_nt(sm, g_ET,0,NR, g_TVT + (long)c*NR,0,R_, g_W,0,D_, NOC,
                 1, D_,D_,NR, -ETA, 1, NOAUX);
        gsync(ph);
    }

    // ph8: H2 = tanh(alpha2*(RD[perm] + x)) -> b0 (row-major r = b*S+s)
    for (long g = gt0; g < (long)R_*D_/4; g += tstep) {
        int d4 = (int)(g % (D_/4)); int r = (int)(g / (D_/4));
        int b = r / S_, s = r - b*S_;
        float4 rd = *(const float4*)(g_b1 + ((long)(s*16+b))*D_ + (long)d4*4);
        float4 xv = *(const float4*)(x + (long)r*D_ + (long)d4*4);
        float4 a2 = *(const float4*)(alpha2 + (long)d4*4);
        float4 h2;
        h2.x = tanhf(a2.x*(rd.x+xv.x)); h2.y = tanhf(a2.y*(rd.y+xv.y));
        h2.z = tanhf(a2.z*(rd.z+xv.z)); h2.w = tanhf(a2.w*(rd.w+xv.w));
        *(float4*)(g_b0 + (long)r*D_ + (long)d4*4) = h2;
    }
    gsync(ph);

    // ph9: U = H2@Wp1^T -> out
    dgemm_nt(sm, g_b0,0,D_, Wp1,0,D_, out,0,D_, NOC, 1, R_,D_,D_, 1.f, 0, NOAUX);
    gsync(ph);

    // ph10: out = gelu(U) * (H2@Wp2^T) + RD[perm] + x
    dgemm_nt(sm, g_b0,0,D_, Wp2,0,D_, out,0,D_, NOC, 1, R_,D_,D_, 1.f, 7,
             (float*)0,0, x, 0);
}

extern "C" void kernel_launch(void* const* d_in, const int* in_sizes, int n_in,
                              void* d_out, int out_size) {
    const float* x       = (const float*)d_in[0];
    const float* noise   = (const float*)d_in[1];
    const float* alpha1  = (const float*)d_in[2];
    const float* alpha2  = (const float*)d_in[3];
    const float* W_map   = (const float*)d_in[4];
    const float* W_state = (const float*)d_in[5];
    const float* W_probe = (const float*)d_in[6];
    const float* W_p1    = (const float*)d_in[7];
    const float* W_p2    = (const float*)d_in[8];
    float* out = (float*)d_out;

    reset_kernel<<<1, 32>>>();
    mega<<<NB, NT>>>(x, noise, alpha1, alpha2, W_map, W_state, W_probe, W_p1, W_p2, out);
}

// round 12
// speedup vs baseline: 2.8360x; 1.6509x over previous
#include <cuda_runtime.h>
#include <cuda_bf16.h>
#include <math.h>

#define B_ 16
#define S_ 1024
#define D_ 1024
#define R_ (B_*S_)           // 16384 rows (step-major: r = s*16 + b)
#define NR 256               // rows per chunk (16 steps x 16 batch)
#define NCH 64               // chunks
#define ETA (0.01f * (2.0f/16384.0f))
#define NB 296               // persistent blocks (2/SM on 148-SM GB300)
#define NT 256
#define SMS 12               // bf16-plane row stride (words)
#define STGW 20              // fp32 stage row stride (floats)
#define DSMEM 65536          // 4 fp32 stages (40KB) + 4 bf16 planes (24KB)

// ---------------- scratch (static device globals, ~500 MB) ----------------
static __device__ float g_b0 [R_*D_];       // STATE -> TV -> H2
static __device__ float g_b1 [R_*D_];       // H -> RDbase -> RD
static __device__ float g_TVT[D_*R_];       // TV^T  [D][R]
static __device__ float g_STT[D_*R_];       // STATE^T [D][R]
static __device__ float g_MT [R_*D_];       // Minv@TV, row-major per chunk
static __device__ float g_ET [D_*R_];       // E^T [D][R] (pre-seeded with E0^T)
static __device__ float g_W  [D_*D_];
static __device__ float g_T  [NCH*NR*NR];
static __device__ float g_TT [NCH*NR*NR];
static __device__ float g_T2 [NCH*NR*NR];
static __device__ float g_CT2[NCH*NR*NR];
static __device__ float g_Sa [NCH*NR*NR];
static __device__ float g_Sb [NCH*NR*NR];   // final Minv
static __device__ float g_Q  [NCH*NR*NR];

static __device__ unsigned g_bar_cnt;
static __device__ unsigned g_bar_phase;

__global__ void reset_kernel() {
    if (threadIdx.x == 0) { g_bar_cnt = 0; g_bar_phase = 0; }
}

__device__ __forceinline__ void gsync(unsigned &ph) {
    __syncthreads();
    if (threadIdx.x == 0) {
        ph++;
        __threadfence();
        unsigned a = atomicAdd(&g_bar_cnt, 1);
        if (a == NB - 1) {
            atomicExch(&g_bar_cnt, 0);
            __threadfence();
            atomicExch(&g_bar_phase, ph);
        } else {
            while (atomicAdd(&g_bar_phase, 0) < ph) __nanosleep(100);
        }
        __threadfence();
    }
    __syncthreads();
}

__device__ __forceinline__ float gelu_exact(float v) {
    return 0.5f*v*(1.0f + erff(v*0.70710678118654752440f));
}

// ---------------- bf16 hi/lo split helpers ----------------
__device__ __forceinline__ unsigned pack_hi(float a, float b, float &ra, float &rb) {
    __nv_bfloat16 ha = __float2bfloat16_rn(a);
    __nv_bfloat16 hb = __float2bfloat16_rn(b);
    ra = a - __bfloat162float(ha);
    rb = b - __bfloat162float(hb);
    return ((unsigned)__bfloat16_as_ushort(hb) << 16) | (unsigned)__bfloat16_as_ushort(ha);
}
__device__ __forceinline__ unsigned pack_lo(float a, float b) {
    return ((unsigned)__bfloat16_as_ushort(__float2bfloat16_rn(b)) << 16)
         |  (unsigned)__bfloat16_as_ushort(__float2bfloat16_rn(a));
}

__device__ __forceinline__ void mma_bf16(float* c,
    unsigned a0, unsigned a1, unsigned a2, unsigned a3, unsigned b0, unsigned b1)
{
    asm volatile(
        "mma.sync.aligned.m16n8k16.row.col.f32.bf16.bf16.f32 "
        "{%0,%1,%2,%3},{%4,%5,%6,%7},{%8,%9},{%0,%1,%2,%3};"
        : "+f"(c[0]), "+f"(c[1]), "+f"(c[2]), "+f"(c[3])
        : "r"(a0), "r"(a1), "r"(a2), "r"(a3), "r"(b0), "r"(b1));
}

__device__ __forceinline__ unsigned smem_u32(const void* p) {
    unsigned a;
    asm("{ .reg .u64 t; cvta.to.shared.u64 t, %1; cvt.u32.u64 %0, t; }" : "=r"(a) : "l"(p));
    return a;
}
__device__ __forceinline__ void cp16(unsigned dst, const float* src) {
    asm volatile("cp.async.cg.shared.global [%0], [%1], 16;" :: "r"(dst), "l"(src) : "memory");
}
#define CP_COMMIT() asm volatile("cp.async.commit_group;" ::: "memory")
#define CP_WAIT1()  asm volatile("cp.async.wait_group 1;" ::: "memory")

// ---------------- bf16-split NT GEMM, cp.async pipelined ---------------------
// C[M][N] = alpha * A[M][K] @ B[N][K]^T (+...). CTA tile 128x128x16, 8 warps.
// Writes C (ldc) and/or CT transposed (ldct).
// epi: 0: C=alpha*acc and/or CT=alpha*acc
//      1: C += alpha*acc
//      3: T=-eta*strictBL(acc) -> C and CT; aux = T + I
//      4: C = -eta*inclBL(acc)
//      5: C = acc + aux[idx]
//      7: C = gelu(C)*acc + RD[perm] + aux2[idx]
//      8: CT += acc            (transposed accumulate)
__device__ void dgemm_nt(float* smf, unsigned smb,
    const float* __restrict__ A0, long sA, int lda,
    const float* __restrict__ B0, long sB, int ldb,
    float* C0, long sC, int ldc,
    float* CT0, long sCT, int ldct,
    int nb, int M, int N, int K,
    float alpha, int epi,
    float* aux, long sAux, const float* __restrict__ aux2, int bofs)
{
    float* AsH = smf + 10240;
    float* AsL = AsH + 128*SMS;
    float* BsH = AsL + 128*SMS;
    float* BsL = BsH + 128*SMS;

    const int tid  = threadIdx.x;
    const int lane = tid & 31;
    const int wid  = tid >> 5;
    const int wm   = wid >> 2;     // 0..1
    const int wn   = wid & 3;      // 0..3
    const int gq   = lane >> 2;    // 0..7
    const int tg   = lane & 3;     // 0..3

    // cp.async mapping: each thread moves 2x16B of A and 2x16B of B per slab
    const int crow = tid >> 2;            // 0..63
    const int ko4  = (tid & 3) << 2;      // k offset in floats: 0,4,8,12
    const int w0b  = (crow*STGW + ko4)*4;       // byte offset in stage
    const int w1b  = w0b + 64*STGW*4;

    // convert mapping
    const int vrow = tid >> 1;            // 0..127
    const int vhf  = tid & 1;             // 0/1

    const int tpmN = N >> 7;
    const int tpm  = (M >> 7) * tpmN;
    const int nt_  = nb * tpm;

    int tstart = blockIdx.x - bofs; if (tstart < 0) tstart += NB;

    for (int t = tstart; t < nt_; t += NB) {
        const int cb = t / tpm;
        const int tt = t - cb*tpm;
        const int bm = tt / tpmN;
        const int bn = tt - bm*tpmN;
        const int m0 = bm << 7, n0 = bn << 7;
        const float* A = A0 + (long)cb*sA;
        const float* B = B0 + (long)cb*sB;

        const float* sA0 = A + (long)(m0 + crow)*lda + ko4;
        const float* sA1 = A + (long)(m0 + 64 + crow)*lda + ko4;
        const float* sB0 = B + (long)(n0 + crow)*ldb + ko4;
        const float* sB1 = B + (long)(n0 + 64 + crow)*ldb + ko4;

        float acc[4][4][4];
        #pragma unroll
        for (int i=0;i<4;i++)
            #pragma unroll
            for (int j=0;j<4;j++)
                #pragma unroll
                for (int q=0;q<4;q++) acc[i][j][q]=0.f;

        const int ns = K >> 4;
        // prologue: stage slabs 0,1
        {
            unsigned oA = smb, oB = smb + 10240;
            cp16(oA + w0b, sA0); cp16(oA + w1b, sA1);
            cp16(oB + w0b, sB0); cp16(oB + w1b, sB1);
            CP_COMMIT();
            oA = smb + 20480; oB = oA + 10240;
            cp16(oA + w0b, sA0 + 16); cp16(oA + w1b, sA1 + 16);
            cp16(oB + w0b, sB0 + 16); cp16(oB + w1b, sB1 + 16);
            CP_COMMIT();
        }

        for (int i = 0; i < ns; i++) {
            const int st = i & 1;
            CP_WAIT1();
            __syncthreads();
            // convert stage st: fp32 -> bf16 hi/lo planes
            {
                const float* sa = smf + st*5120 + vrow*STGW + vhf*8;
                const float* sb = sa + 2560;
                float4 f0 = *(const float4*)sa;
                float4 f1 = *(const float4*)(sa + 4);
                uint4 hv, lv; float r1,r2,r3,r4,r5,r6,r7,r8;
                hv.x = pack_hi(f0.x,f0.y,r1,r2); hv.y = pack_hi(f0.z,f0.w,r3,r4);
                hv.z = pack_hi(f1.x,f1.y,r5,r6); hv.w = pack_hi(f1.z,f1.w,r7,r8);
                lv.x = pack_lo(r1,r2); lv.y = pack_lo(r3,r4);
                lv.z = pack_lo(r5,r6); lv.w = pack_lo(r7,r8);
                *(uint4*)(AsH + vrow*SMS + vhf*4) = hv;
                *(uint4*)(AsL + vrow*SMS + vhf*4) = lv;
                f0 = *(const float4*)sb;
                f1 = *(const float4*)(sb + 4);
                hv.x = pack_hi(f0.x,f0.y,r1,r2); hv.y = pack_hi(f0.z,f0.w,r3,r4);
                hv.z = pack_hi(f1.x,f1.y,r5,r6); hv.w = pack_hi(f1.z,f1.w,r7,r8);
                lv.x = pack_lo(r1,r2); lv.y = pack_lo(r3,r4);
                lv.z = pack_lo(r5,r6); lv.w = pack_lo(r7,r8);
                *(uint4*)(BsH + vrow*SMS + vhf*4) = hv;
                *(uint4*)(BsL + vrow*SMS + vhf*4) = lv;
            }
            __syncthreads();
            // refill this stage with slab i+2 (safe: all reads of it are done)
            if (i + 2 < ns) {
                const int ks = (i + 2) << 4;
                unsigned oA = smb + st*20480, oB = oA + 10240;
                cp16(oA + w0b, sA0 + ks); cp16(oA + w1b, sA1 + ks);
                cp16(oB + w0b, sB0 + ks); cp16(oB + w1b, sB1 + ks);
            }
            CP_COMMIT();
            // compute one k16 slab: 48 MMAs
            unsigned bh[4][2], bl[4][2];
            #pragma unroll
            for (int nt=0; nt<4; nt++) {
                int bnr = (wn*32 + nt*8 + gq)*SMS;
                bh[nt][0] = __float_as_uint(BsH[bnr + tg]);
                bh[nt][1] = __float_as_uint(BsH[bnr + tg + 4]);
                bl[nt][0] = __float_as_uint(BsL[bnr + tg]);
                bl[nt][1] = __float_as_uint(BsL[bnr + tg + 4]);
            }
            #pragma unroll
            for (int mt=0; mt<4; mt++) {
                int am = (wm*64 + mt*16 + gq)*SMS;
                unsigned ah0 = __float_as_uint(AsH[am + tg]);
                unsigned ah1 = __float_as_uint(AsH[am + 8*SMS + tg]);
                unsigned ah2 = __float_as_uint(AsH[am + tg + 4]);
                unsigned ah3 = __float_as_uint(AsH[am + 8*SMS + tg + 4]);
                unsigned al0 = __float_as_uint(AsL[am + tg]);
                unsigned al1 = __float_as_uint(AsL[am + 8*SMS + tg]);
                unsigned al2 = __float_as_uint(AsL[am + tg + 4]);
                unsigned al3 = __float_as_uint(AsL[am + 8*SMS + tg + 4]);
                #pragma unroll
                for (int nt=0; nt<4; nt++) {
                    mma_bf16(acc[mt][nt], ah0,ah1,ah2,ah3, bh[nt][0],bh[nt][1]);
                    mma_bf16(acc[mt][nt], ah0,ah1,ah2,ah3, bl[nt][0],bl[nt][1]);
                    mma_bf16(acc[mt][nt], al0,al1,al2,al3, bh[nt][0],bh[nt][1]);
                }
            }
        }

        // ---- epilogue over fragment (r,c) mapping ----
        float* C    = C0  ? C0  + (long)cb*sC   : (float*)0;
        float* CT   = CT0 ? CT0 + (long)cb*sCT  : (float*)0;
        float* auxc = aux ? aux + (long)cb*sAux : (float*)0;
        #pragma unroll
        for (int mt=0; mt<4; mt++) {
            #pragma unroll
            for (int nt=0; nt<4; nt++) {
                #pragma unroll
                for (int rg=0; rg<4; rg++) {
                    int r = m0 + wm*64 + mt*16 + gq + ((rg>>1)?8:0);
                    int c = n0 + wn*32 + nt*8  + 2*tg + (rg&1);
                    float v = acc[mt][nt][rg];
                    long idx = (long)r*ldc + c;
                    if (epi == 0) {
                        float val = alpha*v;
                        if (C)  C[idx] = val;
                        if (CT) CT[(long)c*ldct + r] = val;
                    } else if (epi == 1) {
                        C[idx] += alpha*v;
                    } else if (epi == 3) {
                        float tv = ((r>>4) > (c>>4)) ? (-ETA)*v : 0.f;
                        C[idx] = tv;
                        CT[(long)c*ldct + r] = tv;
                        auxc[idx] = tv + ((r==c) ? 1.f : 0.f);
                    } else if (epi == 4) {
                        C[idx] = ((r>>4) >= (c>>4)) ? (-ETA)*v : 0.f;
                    } else if (epi == 5) {
                        C[idx] = v + auxc[idx];
                    } else if (epi == 7) {
                        int b = r/S_, s = r - b*S_;
                        float u = C[idx];
                        C[idx] = gelu_exact(u)*v + g_b1[((long)(s*16+b))*D_ + c] + aux2[idx];
                    } else { // epi == 8
                        CT[(long)c*ldct + r] += v;
                    }
                }
            }
        }
    }
}

#define DG(A0,sA,lda,B0,sB,ldb,C0,sC,ldc,CT0,sCT,ldct,nb,M,N,K,al,epi,aux,sAux,aux2,bofs) \
    dgemm_nt(smf, smb, A0,sA,lda, B0,sB,ldb, C0,sC,ldc, CT0,sCT,ldct, \
             nb,M,N,K, al,epi, aux,sAux, aux2, bofs)
#define NP (float*)0
#define NCP (const float*)0

// ---------------- the mega-kernel ----------------
__global__ void __launch_bounds__(NT, 2)
mega(const float* __restrict__ x, const float* __restrict__ noise,
     const float* __restrict__ alpha1, const float* __restrict__ alpha2,
     const float* __restrict__ Wmap, const float* __restrict__ Wstate,
     const float* __restrict__ Wprobe, const float* __restrict__ Wp1,
     const float* __restrict__ Wp2, float* __restrict__ out)
{
    extern __shared__ __align__(16) float smf[];
    const unsigned smb = smem_u32(smf);
    unsigned ph = 0;
    const long tstep = (long)NB*NT;
    const long gt0 = (long)blockIdx.x*NT + threadIdx.x;

    // ph0: W copy + H = tanh(alpha1*x) (step-major permuted) -> b1
    for (long g = gt0; g < (long)D_*D_/4; g += tstep)
        *(float4*)(g_W + g*4) = *(const float4*)(Wmap + g*4);
    for (long g = gt0; g < (long)R_*D_/4; g += tstep) {
        int d4 = (int)(g % (D_/4)); int r = (int)(g / (D_/4));
        int s = r >> 4, b = r & 15;
        float4 xv = *(const float4*)(x + ((long)b*S_ + s)*D_ + (long)d4*4);
        float4 a  = *(const float4*)(alpha1 + (long)d4*4);
        float4 h;
        h.x = tanhf(a.x*xv.x); h.y = tanhf(a.y*xv.y);
        h.z = tanhf(a.z*xv.z); h.w = tanhf(a.w*xv.w);
        *(float4*)(g_b1 + (long)r*D_ + (long)d4*4) = h;
    }
    gsync(ph);

    // ph1: STATE = H@Ws^T -> b0 ; PROBE = H@Wp^T -> out
    DG(g_b1,0,D_, Wstate,0,D_, g_b0,0,D_, NP,0,0, 1, R_,D_,D_, 1.f, 0, NP,0, NCP, 0);
    DG(g_b1,0,D_, Wprobe,0,D_, out, 0,D_, NP,0,0, 1, R_,D_,D_, 1.f, 0, NP,0, NCP, 0);
    gsync(ph);

    // ph2: TV = STATE + noise (in place) ; TVT and STT transposes (32x32 tiles)
    {
        float (*ts)[33] = (float (*)[33])smf;          // TV tile
        float (*us)[33] = (float (*)[33])(smf + 2200); // STATE tile
        const int rl = threadIdx.x >> 3;
        const int c4 = (threadIdx.x & 7) << 2;
        for (int t = blockIdx.x; t < (R_/32)*(D_/32); t += NB) {
            int rt = t >> 5;
            int ct = t & 31;
            long gr = (long)rt*32 + rl;
            int s = (int)(gr>>4), b = (int)(gr&15);
            float4 st = *(const float4*)(g_b0 + gr*D_ + ct*32 + c4);
            float4 nz = *(const float4*)(noise + ((long)b*S_+s)*D_ + ct*32 + c4);
            us[rl][c4+0]=st.x; us[rl][c4+1]=st.y; us[rl][c4+2]=st.z; us[rl][c4+3]=st.w;
            st.x+=nz.x; st.y+=nz.y; st.z+=nz.z; st.w+=nz.w;
            *(float4*)(g_b0 + gr*D_ + ct*32 + c4) = st;
            ts[rl][c4+0]=st.x; ts[rl][c4+1]=st.y; ts[rl][c4+2]=st.z; ts[rl][c4+3]=st.w;
            __syncthreads();
            float4 o;
            o.x = ts[c4+0][rl]; o.y = ts[c4+1][rl];
            o.z = ts[c4+2][rl]; o.w = ts[c4+3][rl];
            *(float4*)(g_TVT + ((long)ct*32 + rl)*R_ + (long)rt*32 + c4) = o;
            o.x = us[c4+0][rl]; o.y = us[c4+1][rl];
            o.z = us[c4+2][rl]; o.w = us[c4+3][rl];
            *(float4*)(g_STT + ((long)ct*32 + rl)*R_ + (long)rt*32 + c4) = o;
            __syncthreads();
        }
    }
    gsync(ph);

    // ph3 (batched): Gram=TV@TV^T -> T,TT,Sa(I+T) ; P=PROBE@TV^T -> Q
    DG(g_b0,(long)NR*D_,D_, g_b0,(long)NR*D_,D_, g_T,(long)NR*NR,NR, g_TT,(long)NR*NR,NR,
       NCH, NR,NR,D_, 1.f, 3, g_Sa,(long)NR*NR, NCP, 0);
    DG(out,(long)NR*D_,D_, g_b0,(long)NR*D_,D_, g_Q,(long)NR*NR,NR, NP,0,0,
       NCH, NR,NR,D_, 1.f, 4, NP,0, NCP, 256);
    gsync(ph);

    // Minv = (I+T)(I+T^2)(I+T^4)(I+T^8), batched (exact: T^16 = 0)
    DG(g_T,(long)NR*NR,NR, g_TT,(long)NR*NR,NR, g_T2,(long)NR*NR,NR, g_CT2,(long)NR*NR,NR,
       NCH, NR,NR,NR, 1.f, 0, NP,0, NCP, 0);                                  // T2 pair
    gsync(ph);
    DG(g_Sa,(long)NR*NR,NR, g_CT2,(long)NR*NR,NR, g_Sb,(long)NR*NR,NR, NP,0,0,
       NCH, NR,NR,NR, 1.f, 5, g_Sa,(long)NR*NR, NCP, 0);                      // Sb=Sa(I+T2)
    DG(g_T2,(long)NR*NR,NR, g_CT2,(long)NR*NR,NR, g_T,(long)NR*NR,NR, g_TT,(long)NR*NR,NR,
       NCH, NR,NR,NR, 1.f, 0, NP,0, NCP, 256);                                // T4 pair
    gsync(ph);
    DG(g_Sb,(long)NR*NR,NR, g_TT,(long)NR*NR,NR, g_Sa,(long)NR*NR,NR, NP,0,0,
       NCH, NR,NR,NR, 1.f, 5, g_Sb,(long)NR*NR, NCP, 0);                      // Sa=Sb(I+T4)
    DG(g_T,(long)NR*NR,NR, g_TT,(long)NR*NR,NR, NP,0,0, g_CT2,(long)NR*NR,NR,
       NCH, NR,NR,NR, 1.f, 0, NP,0, NCP, 256);                                // T8^T
    gsync(ph);
    DG(g_Sa,(long)NR*NR,NR, g_CT2,(long)NR*NR,NR, g_Sb,(long)NR*NR,NR, NP,0,0,
       NCH, NR,NR,NR, 1.f, 5, g_Sa,(long)NR*NR, NCP, 0);                      // Minv in Sb
    gsync(ph);

    // ph8 (batched): MT = Minv@TV (row-major) ; ET seeded with E0^T = -(Minv@STATE)^T
    DG(g_Sb,(long)NR*NR,NR, g_TVT,(long)NR,R_, g_MT,(long)NR*D_,D_, NP,0,0,
       NCH, NR,D_,NR, 1.f, 0, NP,0, NCP, 0);
    DG(g_Sb,(long)NR*NR,NR, g_STT,(long)NR,R_, NP,0,0, g_ET,(long)NR,R_,
       NCH, NR,D_,NR, -1.f, 0, NP,0, NCP, 0);
    gsync(ph);

    // Sequential W-dependent loop: 2 phases per chunk
    for (int c = 0; c < NCH; c++) {
        const long off = (long)c*NR*D_;
        // phA: E_c = MT_c@W^T + E0_c (into ET, transposed accumulate)
        //      RDbase_c = PROBE_c@W^T -> b1
        DG(g_MT+off,0,D_, g_W,0,D_, NP,0,0, g_ET + (long)c*NR,0,R_,
           1, NR,D_,D_, 1.f, 8, NP,0, NCP, 0);
        DG(out+off,0,D_, g_W,0,D_, g_b1+off,0,D_, NP,0,0,
           1, NR,D_,D_, 1.f, 0, NP,0, NCP, 16);
        gsync(ph);
        // phB: W += -eta * E_c^T @ TV_c
        DG(g_ET + (long)c*NR,0,R_, g_TVT + (long)c*NR,0,R_, g_W,0,D_, NP,0,0,
           1, D_,D_,NR, -ETA, 1, NP,0, NCP, 0);
        gsync(ph);
    }

    // batched: RD += Q_c @ E_c  (uses ET as B operand)
    DG(g_Q,(long)NR*NR,NR, g_ET,(long)NR,R_, g_b1,(long)NR*D_,D_, NP,0,0,
       NCH, NR,D_,NR, 1.f, 1, NP,0, NCP, 0);
    gsync(ph);

    // H2 = tanh(alpha2*(RD[perm] + x)) -> b0 (row-major r = b*S+s)
    for (long g = gt0; g < (long)R_*D_/4; g += tstep) {
        int d4 = (int)(g % (D_/4)); int r = (int)(g / (D_/4));
        int b = r / S_, s = r - b*S_;
        float4 rd = *(const float4*)(g_b1 + ((long)(s*16+b))*D_ + (long)d4*4);
        float4 xv = *(const float4*)(x + (long)r*D_ + (long)d4*4);
        float4 a2 = *(const float4*)(alpha2 + (long)d4*4);
        float4 h2;
        h2.x = tanhf(a2.x*(rd.x+xv.x)); h2.y = tanhf(a2.y*(rd.y+xv.y));
        h2.z = tanhf(a2.z*(rd.z+xv.z)); h2.w = tanhf(a2.w*(rd.w+xv.w));
        *(float4*)(g_b0 + (long)r*D_ + (long)d4*4) = h2;
    }
    gsync(ph);

    // U = H2@Wp1^T -> out
    DG(g_b0,0,D_, Wp1,0,D_, out,0,D_, NP,0,0, 1, R_,D_,D_, 1.f, 0, NP,0, NCP, 0);
    gsync(ph);

    // out = gelu(U) * (H2@Wp2^T) + RD[perm] + x
    DG(g_b0,0,D_, Wp2,0,D_, out,0,D_, NP,0,0, 1, R_,D_,D_, 1.f, 7, NP,0, x, 0);
}

extern "C" void kernel_launch(void* const* d_in, const int* in_sizes, int n_in,
                              void* d_out, int out_size) {
    const float* x       = (const float*)d_in[0];
    const float* noise   = (const float*)d_in[1];
    const float* alpha1  = (const float*)d_in[2];
    const float* alpha2  = (const float*)d_in[3];
    const float* W_map   = (const float*)d_in[4];
    const float* W_state = (const float*)d_in[5];
    const float* W_probe = (const float*)d_in[6];
    const float* W_p1    = (const float*)d_in[7];
    const float* W_p2    = (const float*)d_in[8];
    float* out = (float*)d_out;

    cudaFuncSetAttribute(mega, cudaFuncAttributeMaxDynamicSharedMemorySize, DSMEM);
    reset_kernel<<<1, 32>>>();
    mega<<<NB, NT, DSMEM>>>(x, noise, alpha1, alpha2, W_map, W_state, W_probe,
                            W_p1, W_p2, out);
}